// round 1
// baseline (speedup 1.0000x reference)
#include <cuda_runtime.h>

#define Bv 4
#define Sv 2048
#define Dv 1024
#define NBv 513
#define PI_F 3.14159265358979323846f

// ---------------- static device scratch (allocation-free rule) ----------------
__device__ float g_q[Bv * Sv * Dv];                 // 32 MB
__device__ float g_k[Bv * Sv * Dv];                 // 32 MB
__device__ float g_v[Bv * Sv * Dv];                 // 32 MB
__device__ float4 g_kv4[Bv * NBv * Sv / 2];         // 33.6 MB, layout [b][bin][s] (complex)
__device__ float4 g_qn4[Bv * Sv * NBv / 2];         // 33.6 MB, layout [b][s][bin] (complex)

__device__ __forceinline__ float2 cmul(float2 a, float2 b) {
    return make_float2(a.x * b.x - a.y * b.y, a.x * b.y + a.y * b.x);
}

// ---------------- GEMM: q/k/v = x @ W^T  (M=8192, N=1024, K=1024) -------------
#define BM 128
#define BN 128
#define BK 16

__global__ __launch_bounds__(256, 2)
void gemm_qkv(const float* __restrict__ X,
              const float* __restrict__ Wq,
              const float* __restrict__ Wk,
              const float* __restrict__ Wv)
{
    const float* W;
    float* Out;
    if (blockIdx.z == 0)      { W = Wq; Out = g_q; }
    else if (blockIdx.z == 1) { W = Wk; Out = g_k; }
    else                      { W = Wv; Out = g_v; }

    __shared__ float As[BK][BM + 4];
    __shared__ float Bs[BK][BN + 4];

    const int tid = threadIdx.x;
    const int bm = blockIdx.y * BM;
    const int bn = blockIdx.x * BN;
    const int tm = (tid >> 4) * 8;
    const int tn = (tid & 15) * 8;

    float acc[8][8];
    #pragma unroll
    for (int i = 0; i < 8; i++)
        #pragma unroll
        for (int j = 0; j < 8; j++) acc[i][j] = 0.f;

    for (int k0 = 0; k0 < 1024; k0 += BK) {
        #pragma unroll
        for (int r = 0; r < 2; r++) {
            int idx = tid + r * 256;     // 0..511 float4 slots
            int row = idx >> 2;          // 0..127
            int kc  = (idx & 3) * 4;     // 0,4,8,12
            float4 a = *(const float4*)(X + (size_t)(bm + row) * 1024 + k0 + kc);
            As[kc + 0][row] = a.x; As[kc + 1][row] = a.y;
            As[kc + 2][row] = a.z; As[kc + 3][row] = a.w;
            float4 b = *(const float4*)(W + (size_t)(bn + row) * 1024 + k0 + kc);
            Bs[kc + 0][row] = b.x; Bs[kc + 1][row] = b.y;
            Bs[kc + 2][row] = b.z; Bs[kc + 3][row] = b.w;
        }
        __syncthreads();
        #pragma unroll
        for (int kk = 0; kk < BK; kk++) {
            float ra[8], rb[8];
            #pragma unroll
            for (int i = 0; i < 8; i++) ra[i] = As[kk][tm + i];
            #pragma unroll
            for (int j = 0; j < 8; j++) rb[j] = Bs[kk][tn + j];
            #pragma unroll
            for (int i = 0; i < 8; i++)
                #pragma unroll
                for (int j = 0; j < 8; j++)
                    acc[i][j] = fmaf(ra[i], rb[j], acc[i][j]);
        }
        __syncthreads();
    }
    #pragma unroll
    for (int i = 0; i < 8; i++) {
        float* p = Out + (size_t)(bm + tm + i) * 1024 + bn + tn;
        *(float4*)(p)     = make_float4(acc[i][0], acc[i][1], acc[i][2], acc[i][3]);
        *(float4*)(p + 4) = make_float4(acc[i][4], acc[i][5], acc[i][6], acc[i][7]);
    }
}

// ---------------- 1024-pt radix-2 FFT in shared memory ------------------------
// Input must be placed at bit-reversed positions; output is natural order.
// tw[t] = exp(sign * 2*pi*i * t / 1024) — sign=-1 forward, +1 inverse (unnormalized).
__device__ __forceinline__ void fft1024(float2* sd, const float2* tw, int tid)
{
    #pragma unroll
    for (int s = 1; s <= 10; s++) {
        const int mh = 1 << (s - 1);
        #pragma unroll
        for (int r = 0; r < 2; r++) {
            int bidx = tid + r * 256;           // 0..511
            int grp = bidx >> (s - 1);
            int pos = bidx & (mh - 1);
            int i0 = (grp << s) + pos;
            int i1 = i0 + mh;
            float2 w = tw[pos << (10 - s)];
            float2 a = sd[i0], b = sd[i1];
            float tr = w.x * b.x - w.y * b.y;
            float ti = w.x * b.y + w.y * b.x;
            sd[i0] = make_float2(a.x + tr, a.y + ti);
            sd[i1] = make_float2(a.x - tr, a.y - ti);
        }
        __syncthreads();
    }
}

__device__ __forceinline__ void fill_tw(float2* tw, float sign, int tid)
{
    for (int t = tid; t < 512; t += 256) {
        float sv, cv;
        __sincosf(sign * (2.f * PI_F) * (float)t * (1.f / 1024.f), &sv, &cv);
        tw[t] = make_float2(cv, sv);
    }
}

// ---------------- fft(k), fft(v) packed; write normalized-K * V ---------------
__global__ void fft_kv_kernel()
{
    __shared__ float2 sd[1024];
    __shared__ float2 tw[512];
    const int tid = threadIdx.x;
    const int row = blockIdx.x;                 // b*2048 + s
    const float* kr = g_k + (size_t)row * Dv;
    const float* vr = g_v + (size_t)row * Dv;

    fill_tw(tw, -1.f, tid);
    for (int d = tid; d < 1024; d += 256)
        sd[__brev(d) >> 22] = make_float2(kr[d], vr[d]);   // z = k + i*v
    __syncthreads();
    fft1024(sd, tw, tid);

    const int b = row >> 11, s = row & 2047;
    float2* out = (float2*)g_kv4 + (size_t)b * NBv * Sv + s;   // stride Sv per bin
    for (int n = tid; n < 513; n += 256) {
        float2 z0 = sd[n];
        float2 z1 = sd[(1024 - n) & 1023];
        // K = (z0 + conj(z1))/2 ; V = (z0 - conj(z1))/(2i)
        float2 K = make_float2(0.5f * (z0.x + z1.x), 0.5f * (z0.y - z1.y));
        float2 V = make_float2(0.5f * (z0.y + z1.y), 0.5f * (z1.x - z0.x));
        float inv = 1.f / (sqrtf(K.x * K.x + K.y * K.y) + 1e-8f);
        float2 Ku = make_float2(K.x * inv, K.y * inv);
        out[(size_t)n * Sv] = cmul(Ku, V);
    }
}

// ---------------- fft(q) two rows packed; write conj(normalized Q) ------------
__global__ void fft_q_kernel()
{
    __shared__ float2 sd[1024];
    __shared__ float2 tw[512];
    const int tid = threadIdx.x;
    const int row0 = blockIdx.x * 2;            // rows row0, row0+1 (same b)
    const float* q0 = g_q + (size_t)row0 * Dv;
    const float* q1 = q0 + Dv;

    fill_tw(tw, -1.f, tid);
    for (int d = tid; d < 1024; d += 256)
        sd[__brev(d) >> 22] = make_float2(q0[d], q1[d]);
    __syncthreads();
    fft1024(sd, tw, tid);

    float2* o0 = (float2*)g_qn4 + (size_t)row0 * NBv;
    float2* o1 = o0 + NBv;
    for (int n = tid; n < 513; n += 256) {
        float2 z0 = sd[n];
        float2 z1 = sd[(1024 - n) & 1023];
        float2 Q0 = make_float2(0.5f * (z0.x + z1.x), 0.5f * (z0.y - z1.y));
        float2 Q1 = make_float2(0.5f * (z0.y + z1.y), 0.5f * (z1.x - z0.x));
        float i0 = 1.f / (sqrtf(Q0.x * Q0.x + Q0.y * Q0.y) + 1e-8f);
        float i1 = 1.f / (sqrtf(Q1.x * Q1.x + Q1.y * Q1.y) + 1e-8f);
        o0[n] = make_float2(Q0.x * i0, -Q0.y * i0);   // conj(normalized)
        o1[n] = make_float2(Q1.x * i1, -Q1.y * i1);
    }
}

// ---------------- inclusive scan over S per (b, bin) --------------------------
__global__ void scan_kernel()
{
    float4* row4 = g_kv4 + (size_t)blockIdx.x * (Sv / 2);   // 2048 complex = 1024 float4
    const int tid = threadIdx.x;

    float4 v4[4];
    #pragma unroll
    for (int i = 0; i < 4; i++) v4[i] = row4[tid * 4 + i];

    float2 inc[8];
    float2 run = make_float2(0.f, 0.f);
    #pragma unroll
    for (int i = 0; i < 8; i++) {
        float2 c = (i & 1) ? make_float2(v4[i >> 1].z, v4[i >> 1].w)
                           : make_float2(v4[i >> 1].x, v4[i >> 1].y);
        run.x += c.x; run.y += c.y;
        inc[i] = run;
    }

    __shared__ float2 ps[256];
    ps[tid] = run;
    __syncthreads();
    for (int off = 1; off < 256; off <<= 1) {
        float2 t = make_float2(0.f, 0.f);
        if (tid >= off) t = ps[tid - off];
        __syncthreads();
        if (tid >= off) { ps[tid].x += t.x; ps[tid].y += t.y; }
        __syncthreads();
    }
    float2 offs = make_float2(ps[tid].x - run.x, ps[tid].y - run.y);  // exclusive prefix

    #pragma unroll
    for (int i = 0; i < 4; i++) {
        float4 o;
        o.x = inc[2 * i].x + offs.x;     o.y = inc[2 * i].y + offs.y;
        o.z = inc[2 * i + 1].x + offs.x; o.w = inc[2 * i + 1].y + offs.y;
        row4[tid * 4 + i] = o;
    }
}

// ---------------- gather, multiply by conj(Q), inverse FFT, write -------------
__global__ void out_kernel(float* __restrict__ out)
{
    __shared__ float2 sd[1024];
    __shared__ float2 tw[512];
    __shared__ float2 X[513];
    const int tid = threadIdx.x;
    const int row = blockIdx.x;
    const int b = row >> 11, s = row & 2047;

    fill_tw(tw, +1.f, tid);                      // inverse twiddles

    const float2* kvp = (const float2*)g_kv4 + (size_t)b * NBv * Sv + s;
    const float2* qnp = (const float2*)g_qn4 + (size_t)row * NBv;
    for (int n = tid; n < 513; n += 256) {
        float2 a = kvp[(size_t)n * Sv];
        X[n] = cmul(a, qnp[n]);                  // qn already conjugated+normalized
    }
    __syncthreads();

    for (int d = tid; d < 1024; d += 256) {
        float2 v = (d <= 512) ? X[d]
                              : make_float2(X[1024 - d].x, -X[1024 - d].y);
        sd[__brev(d) >> 22] = v;
    }
    __syncthreads();
    fft1024(sd, tw, tid);                        // unnormalized inverse DFT

    float* orow = out + (size_t)row * Dv;
    const float scale = 1.f / 1024.f;
    for (int d = tid; d < 1024; d += 256)
        orow[d] = sd[d].x * scale;
}

// ---------------- launch ------------------------------------------------------
extern "C" void kernel_launch(void* const* d_in, const int* in_sizes, int n_in,
                              void* d_out, int out_size)
{
    (void)in_sizes; (void)n_in; (void)out_size;
    const float* x  = (const float*)d_in[0];
    const float* Wq = (const float*)d_in[1];
    const float* Wk = (const float*)d_in[2];
    const float* Wv = (const float*)d_in[3];
    float* out = (float*)d_out;

    dim3 gg(1024 / BN, (Bv * Sv) / BM, 3);
    gemm_qkv<<<gg, 256>>>(x, Wq, Wk, Wv);
    fft_kv_kernel<<<Bv * Sv, 256>>>();
    fft_q_kernel<<<(Bv * Sv) / 2, 256>>>();
    scan_kernel<<<Bv * NBv, 256>>>();
    out_kernel<<<Bv * Sv, 256>>>(out);
}

// round 4
// speedup vs baseline: 1.8166x; 1.8166x over previous
#include <cuda_runtime.h>
#include <cuda_bf16.h>
#include <cstdint>

#define Bv 4
#define Sv 2048
#define Dv 1024
#define NBv 513
#define Kx 3072            // tripled K for bf16x3 compensated GEMM
#define N3 3072            // fused output width (q|k|v)
#define PI_F 3.14159265358979323846f

// ---------------- static device scratch (allocation-free rule) ----------------
__device__ float g_qkv[(size_t)Bv * Sv * N3];        // 96 MB: [row][q|k|v]
__device__ float4 g_kv4[Bv * NBv * Sv / 2];          // 33.6 MB, layout [b][bin][s]
__device__ float4 g_qn4[Bv * Sv * NBv / 2];          // 33.6 MB, layout [b][s][bin]
__device__ __align__(16) __nv_bfloat16 g_A3[(size_t)Bv * Sv * Kx];   // 48 MB
__device__ __align__(16) __nv_bfloat16 g_B3[(size_t)N3 * Kx];        // 18 MB

__device__ __forceinline__ float2 cmul(float2 a, float2 b) {
    return make_float2(a.x * b.x - a.y * b.y, a.x * b.y + a.y * b.x);
}

__device__ __forceinline__ uint32_t smem_u32(const void* p) {
    uint32_t a;
    asm("{ .reg .u64 t; cvta.to.shared.u64 t, %1; cvt.u32.u64 %0, t; }" : "=r"(a) : "l"(p));
    return a;
}
__device__ __forceinline__ void cp16(uint32_t s, const void* g) {
    asm volatile("cp.async.cg.shared.global [%0], [%1], 16;" :: "r"(s), "l"(g));
}
#define CP_COMMIT() asm volatile("cp.async.commit_group;" ::: "memory")
#define CP_WAIT(n)  asm volatile("cp.async.wait_group %0;" :: "n"(n) : "memory")

__device__ __forceinline__ void mma16816(float* c, const uint32_t* a, const uint32_t* b) {
    asm volatile(
        "mma.sync.aligned.m16n8k16.row.col.f32.bf16.bf16.f32 "
        "{%0,%1,%2,%3}, {%4,%5,%6,%7}, {%8,%9}, {%0,%1,%2,%3};"
        : "+f"(c[0]), "+f"(c[1]), "+f"(c[2]), "+f"(c[3])
        : "r"(a[0]), "r"(a[1]), "r"(a[2]), "r"(a[3]), "r"(b[0]), "r"(b[1]));
}

// ================= bf16 hi/lo split conversion kernels ========================
// A3[m, 0:1024]=hi(x), A3[m,1024:2048]=hi(x), A3[m,2048:3072]=lo(x)
__global__ void convert_x(const float* __restrict__ X)
{
    size_t i4 = (size_t)blockIdx.x * blockDim.x + threadIdx.x;
    float4 x = ((const float4*)X)[i4];
    size_t m = i4 >> 8;
    size_t kc = (i4 & 255) * 4;
    __nv_bfloat16 h0 = __float2bfloat16_rn(x.x), h1 = __float2bfloat16_rn(x.y);
    __nv_bfloat16 h2 = __float2bfloat16_rn(x.z), h3 = __float2bfloat16_rn(x.w);
    __nv_bfloat16 l0 = __float2bfloat16_rn(x.x - __bfloat162float(h0));
    __nv_bfloat16 l1 = __float2bfloat16_rn(x.y - __bfloat162float(h1));
    __nv_bfloat16 l2 = __float2bfloat16_rn(x.z - __bfloat162float(h2));
    __nv_bfloat16 l3 = __float2bfloat16_rn(x.w - __bfloat162float(h3));
    __nv_bfloat16* row = g_A3 + m * Kx;
    __nv_bfloat162 ha = __halves2bfloat162(h0, h1), hb = __halves2bfloat162(h2, h3);
    __nv_bfloat162 la = __halves2bfloat162(l0, l1), lb = __halves2bfloat162(l2, l3);
    *(__nv_bfloat162*)(row + kc) = ha;          *(__nv_bfloat162*)(row + kc + 2) = hb;
    *(__nv_bfloat162*)(row + 1024 + kc) = ha;   *(__nv_bfloat162*)(row + 1024 + kc + 2) = hb;
    *(__nv_bfloat162*)(row + 2048 + kc) = la;   *(__nv_bfloat162*)(row + 2048 + kc + 2) = lb;
}

// B3 row (z*1024+n): [0:1024]=hi(w), [1024:2048]=lo(w), [2048:3072]=hi(w)
__global__ void convert_w(const float* __restrict__ W0,
                          const float* __restrict__ W1,
                          const float* __restrict__ W2)
{
    const float* W = (blockIdx.y == 0) ? W0 : (blockIdx.y == 1) ? W1 : W2;
    size_t i4 = (size_t)blockIdx.x * blockDim.x + threadIdx.x;
    float4 x = ((const float4*)W)[i4];
    size_t n = i4 >> 8;
    size_t kc = (i4 & 255) * 4;
    __nv_bfloat16 h0 = __float2bfloat16_rn(x.x), h1 = __float2bfloat16_rn(x.y);
    __nv_bfloat16 h2 = __float2bfloat16_rn(x.z), h3 = __float2bfloat16_rn(x.w);
    __nv_bfloat16 l0 = __float2bfloat16_rn(x.x - __bfloat162float(h0));
    __nv_bfloat16 l1 = __float2bfloat16_rn(x.y - __bfloat162float(h1));
    __nv_bfloat16 l2 = __float2bfloat16_rn(x.z - __bfloat162float(h2));
    __nv_bfloat16 l3 = __float2bfloat16_rn(x.w - __bfloat162float(h3));
    __nv_bfloat16* row = g_B3 + ((size_t)blockIdx.y * Dv + n) * Kx;
    __nv_bfloat162 ha = __halves2bfloat162(h0, h1), hb = __halves2bfloat162(h2, h3);
    __nv_bfloat162 la = __halves2bfloat162(l0, l1), lb = __halves2bfloat162(l2, l3);
    *(__nv_bfloat162*)(row + kc) = ha;          *(__nv_bfloat162*)(row + kc + 2) = hb;
    *(__nv_bfloat162*)(row + 1024 + kc) = la;   *(__nv_bfloat162*)(row + 1024 + kc + 2) = lb;
    *(__nv_bfloat162*)(row + 2048 + kc) = ha;   *(__nv_bfloat162*)(row + 2048 + kc + 2) = hb;
}

// ================= HMMA bf16 GEMM: g_qkv = A3 @ B3^T ==========================
// CTA tile 128x128, BK=64, cp.async double buffer, 8 warps of 64x32.
#define BM 128
#define BN 128
#define BKC 64
#define NCH (Kx / BKC)        // 48
#define AST 72                // smem row stride, bf16 units (conflict-free)
#define STG (BM * AST * 2)    // 18432 B per tile stage
#define GEMM_SMEM (4 * STG)   // 73728 B

__global__ __launch_bounds__(256, 2) void gemm_mma()
{
    extern __shared__ char smem[];
    const uint32_t sb = smem_u32(smem);
    const int tid = threadIdx.x;
    const int bm = blockIdx.y * BM;
    const int bn = blockIdx.x * BN;

    const int lane = tid & 31, wid = tid >> 5;
    const int g = lane >> 2, tig = lane & 3;
    const int wm = (wid >> 2) * 64, wn = (wid & 3) * 32;

    float acc[4][4][4];
    #pragma unroll
    for (int mt = 0; mt < 4; mt++)
        #pragma unroll
        for (int nt = 0; nt < 4; nt++)
            #pragma unroll
            for (int i = 0; i < 4; i++) acc[mt][nt][i] = 0.f;

    auto issue = [&](int ch, int buf) {
        const uint32_t offA = sb + (2 * buf) * STG;
        const uint32_t offB = sb + (2 * buf + 1) * STG;
        const size_t koff = (size_t)ch * BKC;
        #pragma unroll
        for (int t = 0; t < 4; t++) {
            int idx = tid + t * 256;
            int r = idx >> 3, c = idx & 7;
            cp16(offA + r * 144 + c * 16, g_A3 + (size_t)(bm + r) * Kx + koff + c * 8);
        }
        #pragma unroll
        for (int t = 0; t < 4; t++) {
            int idx = tid + t * 256;
            int r = idx >> 3, c = idx & 7;
            cp16(offB + r * 144 + c * 16, g_B3 + (size_t)(bn + r) * Kx + koff + c * 8);
        }
        CP_COMMIT();
    };

    issue(0, 0);
    for (int ch = 0; ch < NCH; ch++) {
        const int cur = ch & 1;
        if (ch + 1 < NCH) {
            issue(ch + 1, cur ^ 1);
            CP_WAIT(1);
        } else {
            CP_WAIT(0);
        }
        __syncthreads();

        const uint32_t* sA = (const uint32_t*)(smem + (2 * cur) * STG);
        const uint32_t* sB = (const uint32_t*)(smem + (2 * cur + 1) * STG);
        #pragma unroll
        for (int ks = 0; ks < 4; ks++) {
            uint32_t af[4][4], bfr[4][2];
            #pragma unroll
            for (int mt = 0; mt < 4; mt++) {
                int w0 = (wm + mt * 16 + g) * 36 + ks * 8 + tig;
                af[mt][0] = sA[w0];       af[mt][1] = sA[w0 + 288];
                af[mt][2] = sA[w0 + 4];   af[mt][3] = sA[w0 + 292];
            }
            #pragma unroll
            for (int nt = 0; nt < 4; nt++) {
                int w0 = (wn + nt * 8 + g) * 36 + ks * 8 + tig;
                bfr[nt][0] = sB[w0];      bfr[nt][1] = sB[w0 + 4];
            }
            #pragma unroll
            for (int mt = 0; mt < 4; mt++)
                #pragma unroll
                for (int nt = 0; nt < 4; nt++)
                    mma16816(acc[mt][nt], af[mt], bfr[nt]);
        }
        __syncthreads();
    }

    #pragma unroll
    for (int mt = 0; mt < 4; mt++) {
        #pragma unroll
        for (int nt = 0; nt < 4; nt++) {
            int row = bm + wm + mt * 16 + g;
            int col = bn + wn + nt * 8 + 2 * tig;
            *(float2*)(g_qkv + (size_t)row * N3 + col) =
                make_float2(acc[mt][nt][0], acc[mt][nt][1]);
            *(float2*)(g_qkv + (size_t)(row + 8) * N3 + col) =
                make_float2(acc[mt][nt][2], acc[mt][nt][3]);
        }
    }
}

// ---------------- 1024-pt radix-2 FFT in shared memory ------------------------
__device__ __forceinline__ void fft1024(float2* sd, const float2* tw, int tid)
{
    #pragma unroll
    for (int s = 1; s <= 10; s++) {
        const int mh = 1 << (s - 1);
        #pragma unroll
        for (int r = 0; r < 2; r++) {
            int bidx = tid + r * 256;
            int grp = bidx >> (s - 1);
            int pos = bidx & (mh - 1);
            int i0 = (grp << s) + pos;
            int i1 = i0 + mh;
            float2 w = tw[pos << (10 - s)];
            float2 a = sd[i0], b = sd[i1];
            float tr = w.x * b.x - w.y * b.y;
            float ti = w.x * b.y + w.y * b.x;
            sd[i0] = make_float2(a.x + tr, a.y + ti);
            sd[i1] = make_float2(a.x - tr, a.y - ti);
        }
        __syncthreads();
    }
}

__device__ __forceinline__ void fill_tw(float2* tw, float sign, int tid)
{
    for (int t = tid; t < 512; t += 256) {
        float sv, cv;
        __sincosf(sign * (2.f * PI_F) * (float)t * (1.f / 1024.f), &sv, &cv);
        tw[t] = make_float2(cv, sv);
    }
}

// ---------------- fft(k), fft(v) packed; write normalized-K * V ---------------
__global__ void fft_kv_kernel()
{
    __shared__ float2 sd[1024];
    __shared__ float2 tw[512];
    const int tid = threadIdx.x;
    const int row = blockIdx.x;
    const float* kr = g_qkv + (size_t)row * N3 + 1024;
    const float* vr = g_qkv + (size_t)row * N3 + 2048;

    fill_tw(tw, -1.f, tid);
    for (int d = tid; d < 1024; d += 256)
        sd[__brev(d) >> 22] = make_float2(kr[d], vr[d]);
    __syncthreads();
    fft1024(sd, tw, tid);

    const int b = row >> 11, s = row & 2047;
    float2* out = (float2*)g_kv4 + (size_t)b * NBv * Sv + s;
    for (int n = tid; n < 513; n += 256) {
        float2 z0 = sd[n];
        float2 z1 = sd[(1024 - n) & 1023];
        float2 K = make_float2(0.5f * (z0.x + z1.x), 0.5f * (z0.y - z1.y));
        float2 V = make_float2(0.5f * (z0.y + z1.y), 0.5f * (z1.x - z0.x));
        float inv = 1.f / (sqrtf(K.x * K.x + K.y * K.y) + 1e-8f);
        float2 Ku = make_float2(K.x * inv, K.y * inv);
        out[(size_t)n * Sv] = cmul(Ku, V);
    }
}

// ---------------- fft(q) two rows packed; write conj(normalized Q) ------------
__global__ void fft_q_kernel()
{
    __shared__ float2 sd[1024];
    __shared__ float2 tw[512];
    const int tid = threadIdx.x;
    const int row0 = blockIdx.x * 2;
    const float* q0 = g_qkv + (size_t)row0 * N3;
    const float* q1 = q0 + N3;

    fill_tw(tw, -1.f, tid);
    for (int d = tid; d < 1024; d += 256)
        sd[__brev(d) >> 22] = make_float2(q0[d], q1[d]);
    __syncthreads();
    fft1024(sd, tw, tid);

    float2* o0 = (float2*)g_qn4 + (size_t)row0 * NBv;
    float2* o1 = o0 + NBv;
    for (int n = tid; n < 513; n += 256) {
        float2 z0 = sd[n];
        float2 z1 = sd[(1024 - n) & 1023];
        float2 Q0 = make_float2(0.5f * (z0.x + z1.x), 0.5f * (z0.y - z1.y));
        float2 Q1 = make_float2(0.5f * (z0.y + z1.y), 0.5f * (z1.x - z0.x));
        float i0 = 1.f / (sqrtf(Q0.x * Q0.x + Q0.y * Q0.y) + 1e-8f);
        float i1 = 1.f / (sqrtf(Q1.x * Q1.x + Q1.y * Q1.y) + 1e-8f);
        o0[n] = make_float2(Q0.x * i0, -Q0.y * i0);
        o1[n] = make_float2(Q1.x * i1, -Q1.y * i1);
    }
}

// ---------------- inclusive scan over S per (b, bin) --------------------------
__global__ void scan_kernel()
{
    float4* row4 = g_kv4 + (size_t)blockIdx.x * (Sv / 2);
    const int tid = threadIdx.x;

    float4 v4[4];
    #pragma unroll
    for (int i = 0; i < 4; i++) v4[i] = row4[tid * 4 + i];

    float2 inc[8];
    float2 run = make_float2(0.f, 0.f);
    #pragma unroll
    for (int i = 0; i < 8; i++) {
        float2 c = (i & 1) ? make_float2(v4[i >> 1].z, v4[i >> 1].w)
                           : make_float2(v4[i >> 1].x, v4[i >> 1].y);
        run.x += c.x; run.y += c.y;
        inc[i] = run;
    }

    __shared__ float2 ps[256];
    ps[tid] = run;
    __syncthreads();
    for (int off = 1; off < 256; off <<= 1) {
        float2 t = make_float2(0.f, 0.f);
        if (tid >= off) t = ps[tid - off];
        __syncthreads();
        if (tid >= off) { ps[tid].x += t.x; ps[tid].y += t.y; }
        __syncthreads();
    }
    float2 offs = make_float2(ps[tid].x - run.x, ps[tid].y - run.y);

    #pragma unroll
    for (int i = 0; i < 4; i++) {
        float4 o;
        o.x = inc[2 * i].x + offs.x;     o.y = inc[2 * i].y + offs.y;
        o.z = inc[2 * i + 1].x + offs.x; o.w = inc[2 * i + 1].y + offs.y;
        row4[tid * 4 + i] = o;
    }
}

// ---------------- gather, multiply by conj(Q), inverse FFT, write -------------
__global__ void out_kernel(float* __restrict__ out)
{
    __shared__ float2 sd[1024];
    __shared__ float2 tw[512];
    __shared__ float2 X[513];
    const int tid = threadIdx.x;
    const int row = blockIdx.x;
    const int b = row >> 11, s = row & 2047;

    fill_tw(tw, +1.f, tid);

    const float2* kvp = (const float2*)g_kv4 + (size_t)b * NBv * Sv + s;
    const float2* qnp = (const float2*)g_qn4 + (size_t)row * NBv;
    for (int n = tid; n < 513; n += 256) {
        float2 a = kvp[(size_t)n * Sv];
        X[n] = cmul(a, qnp[n]);
    }
    __syncthreads();

    for (int d = tid; d < 1024; d += 256) {
        float2 v = (d <= 512) ? X[d]
                              : make_float2(X[1024 - d].x, -X[1024 - d].y);
        sd[__brev(d) >> 22] = v;
    }
    __syncthreads();
    fft1024(sd, tw, tid);

    float* orow = out + (size_t)row * Dv;
    const float scale = 1.f / 1024.f;
    for (int d = tid; d < 1024; d += 256)
        orow[d] = sd[d].x * scale;
}

// ---------------- launch ------------------------------------------------------
extern "C" void kernel_launch(void* const* d_in, const int* in_sizes, int n_in,
                              void* d_out, int out_size)
{
    (void)in_sizes; (void)n_in; (void)out_size;
    const float* x  = (const float*)d_in[0];
    const float* Wq = (const float*)d_in[1];
    const float* Wk = (const float*)d_in[2];
    const float* Wv = (const float*)d_in[3];
    float* out = (float*)d_out;

    cudaFuncSetAttribute(gemm_mma, cudaFuncAttributeMaxDynamicSharedMemorySize, GEMM_SMEM);

    convert_x<<<(Bv * Sv * Dv / 4) / 256, 256>>>(x);
    convert_w<<<dim3((Dv * Dv / 4) / 256, 3), 256>>>(Wq, Wk, Wv);

    dim3 gg(N3 / BN, (Bv * Sv) / BM);    // (24, 64)
    gemm_mma<<<gg, 256, GEMM_SMEM>>>();

    fft_kv_kernel<<<Bv * Sv, 256>>>();
    fft_q_kernel<<<(Bv * Sv) / 2, 256>>>();
    scan_kernel<<<Bv * NBv, 256>>>();
    out_kernel<<<Bv * Sv, 256>>>(out);
}

// round 5
// speedup vs baseline: 2.2578x; 1.2428x over previous
#include <cuda_runtime.h>
#include <cuda_bf16.h>
#include <cstdint>

#define Bv 4
#define Sv 2048
#define Dv 1024
#define NBv 513
#define Kx 3072            // tripled K for bf16x3 compensated GEMM
#define N3 3072            // fused output width (q|k|v)
#define PI_F 3.14159265358979323846f

// ---------------- static device scratch (allocation-free rule) ----------------
__device__ float g_qkv[(size_t)Bv * Sv * N3];        // 96 MB: [row][q|k|v]
__device__ float4 g_kv4[Bv * NBv * Sv / 2];          // 33.6 MB, layout [b][bin][s]
__device__ float4 g_qn4[Bv * Sv * NBv / 2];          // 33.6 MB, layout [b][s][bin]
__device__ float2 g_x[(size_t)Bv * Sv * NBv];        // 33.6 MB, layout [b][s][bin]
__device__ __align__(16) __nv_bfloat16 g_A3[(size_t)Bv * Sv * Kx];   // 48 MB
__device__ __align__(16) __nv_bfloat16 g_B3[(size_t)N3 * Kx];        // 18 MB

__device__ __forceinline__ float2 cmul(float2 a, float2 b) {
    return make_float2(a.x * b.x - a.y * b.y, a.x * b.y + a.y * b.x);
}

__device__ __forceinline__ uint32_t smem_u32(const void* p) {
    uint32_t a;
    asm("{ .reg .u64 t; cvta.to.shared.u64 t, %1; cvt.u32.u64 %0, t; }" : "=r"(a) : "l"(p));
    return a;
}
__device__ __forceinline__ void cp16(uint32_t s, const void* g) {
    asm volatile("cp.async.cg.shared.global [%0], [%1], 16;" :: "r"(s), "l"(g));
}
#define CP_COMMIT() asm volatile("cp.async.commit_group;" ::: "memory")
#define CP_WAIT(n)  asm volatile("cp.async.wait_group %0;" :: "n"(n) : "memory")

__device__ __forceinline__ void mma16816(float* c, const uint32_t* a, const uint32_t* b) {
    asm volatile(
        "mma.sync.aligned.m16n8k16.row.col.f32.bf16.bf16.f32 "
        "{%0,%1,%2,%3}, {%4,%5,%6,%7}, {%8,%9}, {%0,%1,%2,%3};"
        : "+f"(c[0]), "+f"(c[1]), "+f"(c[2]), "+f"(c[3])
        : "r"(a[0]), "r"(a[1]), "r"(a[2]), "r"(a[3]), "r"(b[0]), "r"(b[1]));
}
__device__ __forceinline__ void ldm_x4(uint32_t* r, uint32_t addr) {
    asm volatile("ldmatrix.sync.aligned.m8n8.x4.shared.b16 {%0,%1,%2,%3}, [%4];"
        : "=r"(r[0]), "=r"(r[1]), "=r"(r[2]), "=r"(r[3]) : "r"(addr));
}

// ================= bf16 hi/lo split conversion kernels ========================
__global__ void convert_x(const float* __restrict__ X)
{
    size_t i4 = (size_t)blockIdx.x * blockDim.x + threadIdx.x;
    float4 x = ((const float4*)X)[i4];
    size_t m = i4 >> 8;
    size_t kc = (i4 & 255) * 4;
    __nv_bfloat16 h0 = __float2bfloat16_rn(x.x), h1 = __float2bfloat16_rn(x.y);
    __nv_bfloat16 h2 = __float2bfloat16_rn(x.z), h3 = __float2bfloat16_rn(x.w);
    __nv_bfloat16 l0 = __float2bfloat16_rn(x.x - __bfloat162float(h0));
    __nv_bfloat16 l1 = __float2bfloat16_rn(x.y - __bfloat162float(h1));
    __nv_bfloat16 l2 = __float2bfloat16_rn(x.z - __bfloat162float(h2));
    __nv_bfloat16 l3 = __float2bfloat16_rn(x.w - __bfloat162float(h3));
    __nv_bfloat16* row = g_A3 + m * Kx;
    __nv_bfloat162 ha = __halves2bfloat162(h0, h1), hb = __halves2bfloat162(h2, h3);
    __nv_bfloat162 la = __halves2bfloat162(l0, l1), lb = __halves2bfloat162(l2, l3);
    *(__nv_bfloat162*)(row + kc) = ha;          *(__nv_bfloat162*)(row + kc + 2) = hb;
    *(__nv_bfloat162*)(row + 1024 + kc) = ha;   *(__nv_bfloat162*)(row + 1024 + kc + 2) = hb;
    *(__nv_bfloat162*)(row + 2048 + kc) = la;   *(__nv_bfloat162*)(row + 2048 + kc + 2) = lb;
}

__global__ void convert_w(const float* __restrict__ W0,
                          const float* __restrict__ W1,
                          const float* __restrict__ W2)
{
    const float* W = (blockIdx.y == 0) ? W0 : (blockIdx.y == 1) ? W1 : W2;
    size_t i4 = (size_t)blockIdx.x * blockDim.x + threadIdx.x;
    float4 x = ((const float4*)W)[i4];
    size_t n = i4 >> 8;
    size_t kc = (i4 & 255) * 4;
    __nv_bfloat16 h0 = __float2bfloat16_rn(x.x), h1 = __float2bfloat16_rn(x.y);
    __nv_bfloat16 h2 = __float2bfloat16_rn(x.z), h3 = __float2bfloat16_rn(x.w);
    __nv_bfloat16 l0 = __float2bfloat16_rn(x.x - __bfloat162float(h0));
    __nv_bfloat16 l1 = __float2bfloat16_rn(x.y - __bfloat162float(h1));
    __nv_bfloat16 l2 = __float2bfloat16_rn(x.z - __bfloat162float(h2));
    __nv_bfloat16 l3 = __float2bfloat16_rn(x.w - __bfloat162float(h3));
    __nv_bfloat16* row = g_B3 + ((size_t)blockIdx.y * Dv + n) * Kx;
    __nv_bfloat162 ha = __halves2bfloat162(h0, h1), hb = __halves2bfloat162(h2, h3);
    __nv_bfloat162 la = __halves2bfloat162(l0, l1), lb = __halves2bfloat162(l2, l3);
    *(__nv_bfloat162*)(row + kc) = ha;          *(__nv_bfloat162*)(row + kc + 2) = hb;
    *(__nv_bfloat162*)(row + 1024 + kc) = la;   *(__nv_bfloat162*)(row + 1024 + kc + 2) = lb;
    *(__nv_bfloat162*)(row + 2048 + kc) = ha;   *(__nv_bfloat162*)(row + 2048 + kc + 2) = hb;
}

// ================= HMMA bf16 GEMM: g_qkv = A3 @ B3^T ==========================
#define BM 128
#define BN 128
#define BKC 64
#define NCH (Kx / BKC)        // 48
#define STG (BM * 72 * 2)     // 18432 B per tile stage (row stride 144 B)
#define GEMM_SMEM (4 * STG)   // 73728 B

__global__ __launch_bounds__(256, 2) void gemm_mma()
{
    extern __shared__ char smem[];
    const uint32_t sb = smem_u32(smem);
    const int tid = threadIdx.x;
    const int bm = blockIdx.y * BM;
    const int bn = blockIdx.x * BN;

    const int lane = tid & 31, wid = tid >> 5;
    const int g = lane >> 2, tig = lane & 3;
    const int wm = (wid >> 2) * 64, wn = (wid & 3) * 32;

    // ldmatrix per-lane row offsets
    const int arow = lane & 15;
    const int ahalf = (lane >> 4) & 1;
    const int brow = (lane & 7) + ((lane >> 4) << 3);
    const int bhalf = (lane >> 3) & 1;

    float acc[4][4][4];
    #pragma unroll
    for (int mt = 0; mt < 4; mt++)
        #pragma unroll
        for (int nt = 0; nt < 4; nt++)
            #pragma unroll
            for (int i = 0; i < 4; i++) acc[mt][nt][i] = 0.f;

    auto issue = [&](int ch, int buf) {
        const uint32_t offA = sb + (2 * buf) * STG;
        const uint32_t offB = sb + (2 * buf + 1) * STG;
        const size_t koff = (size_t)ch * BKC;
        #pragma unroll
        for (int t = 0; t < 4; t++) {
            int idx = tid + t * 256;
            int r = idx >> 3, c = idx & 7;
            cp16(offA + r * 144 + c * 16, g_A3 + (size_t)(bm + r) * Kx + koff + c * 8);
        }
        #pragma unroll
        for (int t = 0; t < 4; t++) {
            int idx = tid + t * 256;
            int r = idx >> 3, c = idx & 7;
            cp16(offB + r * 144 + c * 16, g_B3 + (size_t)(bn + r) * Kx + koff + c * 8);
        }
        CP_COMMIT();
    };

    issue(0, 0);
    for (int ch = 0; ch < NCH; ch++) {
        const int cur = ch & 1;
        if (ch + 1 < NCH) {
            issue(ch + 1, cur ^ 1);
            CP_WAIT(1);
        } else {
            CP_WAIT(0);
        }
        __syncthreads();

        const uint32_t sA32 = sb + (2 * cur) * STG;
        const uint32_t sB32 = sb + (2 * cur + 1) * STG;
        #pragma unroll
        for (int ks = 0; ks < 4; ks++) {
            uint32_t af[4][4], bfr[2][4];
            #pragma unroll
            for (int mt = 0; mt < 4; mt++)
                ldm_x4(af[mt], sA32 + (wm + mt * 16 + arow) * 144 + ks * 32 + ahalf * 16);
            #pragma unroll
            for (int np = 0; np < 2; np++)
                ldm_x4(bfr[np], sB32 + (wn + np * 16 + brow) * 144 + ks * 32 + bhalf * 16);
            #pragma unroll
            for (int mt = 0; mt < 4; mt++)
                #pragma unroll
                for (int nt = 0; nt < 4; nt++)
                    mma16816(acc[mt][nt], af[mt], &bfr[nt >> 1][(nt & 1) * 2]);
        }
        __syncthreads();
    }

    #pragma unroll
    for (int mt = 0; mt < 4; mt++) {
        #pragma unroll
        for (int nt = 0; nt < 4; nt++) {
            int row = bm + wm + mt * 16 + g;
            int col = bn + wn + nt * 8 + 2 * tig;
            *(float2*)(g_qkv + (size_t)row * N3 + col) =
                make_float2(acc[mt][nt][0], acc[mt][nt][1]);
            *(float2*)(g_qkv + (size_t)(row + 8) * N3 + col) =
                make_float2(acc[mt][nt][2], acc[mt][nt][3]);
        }
    }
}

// ---------------- 1024-pt radix-4 Stockham FFT in shared memory ---------------
// Natural-order in, natural-order out. Result ends in bB. TW[t]=exp(-2pi i t/1024).
__device__ __forceinline__ void fft1024_r4(float2* bA, float2* bB, const float2* TW,
                                           int tid, int inverse)
{
    float2* in = bA;
    float2* out = bB;
    #pragma unroll
    for (int st = 0; st < 5; st++) {
        const int Ns = 1 << (2 * st);
        float2 v0 = in[tid];
        float2 v1 = in[tid + 256];
        float2 v2 = in[tid + 512];
        float2 v3 = in[tid + 768];
        const int t = tid & (Ns - 1);
        if (st > 0) {
            const int ti = t << (8 - 2 * st);      // t * (256/Ns)
            float2 w1 = TW[ti], w2 = TW[2 * ti], w3 = TW[3 * ti];
            if (inverse) { w1.y = -w1.y; w2.y = -w2.y; w3.y = -w3.y; }
            v1 = cmul(v1, w1); v2 = cmul(v2, w2); v3 = cmul(v3, w3);
        }
        float2 a  = make_float2(v0.x + v2.x, v0.y + v2.y);
        float2 bq = make_float2(v0.x - v2.x, v0.y - v2.y);
        float2 c  = make_float2(v1.x + v3.x, v1.y + v3.y);
        float2 d  = make_float2(v1.x - v3.x, v1.y - v3.y);
        float2 dr = inverse ? make_float2(-d.y, d.x) : make_float2(d.y, -d.x);
        const int idx = ((tid >> (2 * st)) << (2 * st + 2)) + t;   // (j/Ns)*4Ns + t
        out[idx]          = make_float2(a.x + c.x,  a.y + c.y);
        out[idx + Ns]     = make_float2(bq.x + dr.x, bq.y + dr.y);
        out[idx + 2 * Ns] = make_float2(a.x - c.x,  a.y - c.y);
        out[idx + 3 * Ns] = make_float2(bq.x - dr.x, bq.y - dr.y);
        __syncthreads();
        float2* tmp = in; in = out; out = tmp;
    }
}

__device__ __forceinline__ void fill_tw768(float2* TW, int tid)
{
    for (int t = tid; t < 768; t += 256) {
        float sv, cv;
        __sincosf(-(2.f * PI_F) * (float)t * (1.f / 1024.f), &sv, &cv);
        TW[t] = make_float2(cv, sv);
    }
}

// ---------------- fft(k), fft(v) packed; write normalized-K * V ---------------
__global__ void fft_kv_kernel()
{
    __shared__ float2 bA[1024], bB[1024], TW[768];
    const int tid = threadIdx.x;
    const int row = blockIdx.x;
    const float* kr = g_qkv + (size_t)row * N3 + 1024;
    const float* vr = g_qkv + (size_t)row * N3 + 2048;

    fill_tw768(TW, tid);
    for (int d = tid; d < 1024; d += 256)
        bA[d] = make_float2(kr[d], vr[d]);          // z = k + i*v
    __syncthreads();
    fft1024_r4(bA, bB, TW, tid, 0);

    const int b = row >> 11, s = row & 2047;
    float2* out = (float2*)g_kv4 + (size_t)b * NBv * Sv + s;
    for (int n = tid; n < 513; n += 256) {
        float2 z0 = bB[n];
        float2 z1 = bB[(1024 - n) & 1023];
        float2 K = make_float2(0.5f * (z0.x + z1.x), 0.5f * (z0.y - z1.y));
        float2 V = make_float2(0.5f * (z0.y + z1.y), 0.5f * (z1.x - z0.x));
        float inv = 1.f / (sqrtf(K.x * K.x + K.y * K.y) + 1e-8f);
        float2 Ku = make_float2(K.x * inv, K.y * inv);
        out[(size_t)n * Sv] = cmul(Ku, V);
    }
}

// ---------------- fft(q) two rows packed; write conj(normalized Q) ------------
__global__ void fft_q_kernel()
{
    __shared__ float2 bA[1024], bB[1024], TW[768];
    const int tid = threadIdx.x;
    const int row0 = blockIdx.x * 2;
    const float* q0 = g_qkv + (size_t)row0 * N3;
    const float* q1 = q0 + N3;

    fill_tw768(TW, tid);
    for (int d = tid; d < 1024; d += 256)
        bA[d] = make_float2(q0[d], q1[d]);
    __syncthreads();
    fft1024_r4(bA, bB, TW, tid, 0);

    float2* o0 = (float2*)g_qn4 + (size_t)row0 * NBv;
    float2* o1 = o0 + NBv;
    for (int n = tid; n < 513; n += 256) {
        float2 z0 = bB[n];
        float2 z1 = bB[(1024 - n) & 1023];
        float2 Q0 = make_float2(0.5f * (z0.x + z1.x), 0.5f * (z0.y - z1.y));
        float2 Q1 = make_float2(0.5f * (z0.y + z1.y), 0.5f * (z1.x - z0.x));
        float i0 = 1.f / (sqrtf(Q0.x * Q0.x + Q0.y * Q0.y) + 1e-8f);
        float i1 = 1.f / (sqrtf(Q1.x * Q1.x + Q1.y * Q1.y) + 1e-8f);
        o0[n] = make_float2(Q0.x * i0, -Q0.y * i0);
        o1[n] = make_float2(Q1.x * i1, -Q1.y * i1);
    }
}

// ---------------- inclusive scan over S per (b, bin) --------------------------
__global__ void scan_kernel()
{
    float4* row4 = g_kv4 + (size_t)blockIdx.x * (Sv / 2);
    const int tid = threadIdx.x;

    float4 v4[4];
    #pragma unroll
    for (int i = 0; i < 4; i++) v4[i] = row4[tid * 4 + i];

    float2 inc[8];
    float2 run = make_float2(0.f, 0.f);
    #pragma unroll
    for (int i = 0; i < 8; i++) {
        float2 c = (i & 1) ? make_float2(v4[i >> 1].z, v4[i >> 1].w)
                           : make_float2(v4[i >> 1].x, v4[i >> 1].y);
        run.x += c.x; run.y += c.y;
        inc[i] = run;
    }

    __shared__ float2 ps[256];
    ps[tid] = run;
    __syncthreads();
    for (int off = 1; off < 256; off <<= 1) {
        float2 t = make_float2(0.f, 0.f);
        if (tid >= off) t = ps[tid - off];
        __syncthreads();
        if (tid >= off) { ps[tid].x += t.x; ps[tid].y += t.y; }
        __syncthreads();
    }
    float2 offs = make_float2(ps[tid].x - run.x, ps[tid].y - run.y);

    #pragma unroll
    for (int i = 0; i < 4; i++) {
        float4 o;
        o.x = inc[2 * i].x + offs.x;     o.y = inc[2 * i].y + offs.y;
        o.z = inc[2 * i + 1].x + offs.x; o.w = inc[2 * i + 1].y + offs.y;
        row4[tid * 4 + i] = o;
    }
}

// ---------------- transpose + conj(Q) multiply: X[b][s][bin] ------------------
__global__ void transp_mult()
{
    __shared__ float2 tile[32][33];
    const int tx = threadIdx.x, ty = threadIdx.y;
    const int b = blockIdx.z;
    const int bin0 = blockIdx.x * 32;
    const int s0 = blockIdx.y * 32;

    const float2* kv = (const float2*)g_kv4 + (size_t)b * NBv * Sv;
    #pragma unroll
    for (int j = 0; j < 4; j++) {
        int bin = bin0 + ty + j * 8;
        if (bin < NBv)
            tile[ty + j * 8][tx] = kv[(size_t)bin * Sv + s0 + tx];
    }
    __syncthreads();

    const float2* qn = (const float2*)g_qn4;
    #pragma unroll
    for (int j = 0; j < 4; j++) {
        int s = s0 + ty + j * 8;
        int bin = bin0 + tx;
        if (bin < NBv) {
            size_t off = ((size_t)b * Sv + s) * NBv + bin;
            g_x[off] = cmul(tile[tx][ty + j * 8], qn[off]);
        }
    }
}

// ---------------- inverse FFT, two rows packed, write real --------------------
__global__ void out_kernel(float* __restrict__ out)
{
    __shared__ float2 bA[1024], bB[1024], TW[768];
    const int tid = threadIdx.x;
    const int row0 = blockIdx.x * 2;

    fill_tw768(TW, tid);
    const float2* X0 = g_x + (size_t)row0 * NBv;
    const float2* X1 = X0 + NBv;
    for (int d = tid; d < 1024; d += 256) {
        float2 x0, x1;
        if (d <= 512) { x0 = X0[d]; x1 = X1[d]; }
        else {
            float2 a0 = X0[1024 - d], a1 = X1[1024 - d];
            x0 = make_float2(a0.x, -a0.y);
            x1 = make_float2(a1.x, -a1.y);
        }
        bA[d] = make_float2(x0.x - x1.y, x0.y + x1.x);   // Z = X0 + i*X1
    }
    __syncthreads();
    fft1024_r4(bA, bB, TW, tid, 1);

    float* o0 = out + (size_t)row0 * Dv;
    float* o1 = o0 + Dv;
    const float scale = 1.f / 1024.f;
    for (int d = tid; d < 1024; d += 256) {
        o0[d] = bB[d].x * scale;
        o1[d] = bB[d].y * scale;
    }
}

// ---------------- launch ------------------------------------------------------
extern "C" void kernel_launch(void* const* d_in, const int* in_sizes, int n_in,
                              void* d_out, int out_size)
{
    (void)in_sizes; (void)n_in; (void)out_size;
    const float* x  = (const float*)d_in[0];
    const float* Wq = (const float*)d_in[1];
    const float* Wk = (const float*)d_in[2];
    const float* Wv = (const float*)d_in[3];
    float* out = (float*)d_out;

    cudaFuncSetAttribute(gemm_mma, cudaFuncAttributeMaxDynamicSharedMemorySize, GEMM_SMEM);

    convert_x<<<(Bv * Sv * Dv / 4) / 256, 256>>>(x);
    convert_w<<<dim3((Dv * Dv / 4) / 256, 3), 256>>>(Wq, Wk, Wv);

    dim3 gg(N3 / BN, (Bv * Sv) / BM);    // (24, 64)
    gemm_mma<<<gg, 256, GEMM_SMEM>>>();

    fft_kv_kernel<<<Bv * Sv, 256>>>();
    fft_q_kernel<<<(Bv * Sv) / 2, 256>>>();
    scan_kernel<<<Bv * NBv, 256>>>();
    transp_mult<<<dim3(17, Sv / 32, Bv), dim3(32, 8)>>>();
    out_kernel<<<(Bv * Sv) / 2, 256>>>(out);
}

// round 6
// speedup vs baseline: 2.5242x; 1.1180x over previous
#include <cuda_runtime.h>
#include <cuda_bf16.h>
#include <cstdint>

#define Bv 4
#define Sv 2048
#define Dv 1024
#define NBv 513
#define Kx 3072            // tripled K for bf16x3 compensated GEMM
#define NOUT 3200          // padded GEMM output width (3*1026 -> 3200)
#define NROW 8192          // Bv*Sv
#define PI_F 3.14159265358979323846f

// ---------------- static device scratch (allocation-free rule) ----------------
__device__ float g_qkv2[(size_t)NROW * NOUT];        // 104.8 MB: spectra q|k|v
__device__ float4 g_kv4[Bv * NBv * Sv / 2];          // 33.6 MB, layout [b][bin][s]
__device__ float2 g_x[(size_t)Bv * Sv * NBv];        // 33.6 MB, layout [b][s][bin]
__device__ __align__(16) __nv_bfloat16 g_A3[(size_t)NROW * Kx];      // 48 MB
__device__ __align__(16) __nv_bfloat16 g_B3[(size_t)NOUT * Kx];      // 19.7 MB
__device__ float g_Wt[3 * Dv * Dv];                  // 12.6 MB, W transposed
__device__ float2 g_Bc2[(size_t)3 * NBv * Dv];       // 12.6 MB, What [z][n][d]

__device__ __forceinline__ float2 cmul(float2 a, float2 b) {
    return make_float2(a.x * b.x - a.y * b.y, a.x * b.y + a.y * b.x);
}

__device__ __forceinline__ uint32_t smem_u32(const void* p) {
    uint32_t a;
    asm("{ .reg .u64 t; cvta.to.shared.u64 t, %1; cvt.u32.u64 %0, t; }" : "=r"(a) : "l"(p));
    return a;
}
__device__ __forceinline__ void cp16(uint32_t s, const void* g) {
    asm volatile("cp.async.cg.shared.global [%0], [%1], 16;" :: "r"(s), "l"(g));
}
#define CP_COMMIT() asm volatile("cp.async.commit_group;" ::: "memory")
#define CP_WAIT(n)  asm volatile("cp.async.wait_group %0;" :: "n"(n) : "memory")

__device__ __forceinline__ void mma16816(float* c, const uint32_t* a, const uint32_t* b) {
    asm volatile(
        "mma.sync.aligned.m16n8k16.row.col.f32.bf16.bf16.f32 "
        "{%0,%1,%2,%3}, {%4,%5,%6,%7}, {%8,%9}, {%0,%1,%2,%3};"
        : "+f"(c[0]), "+f"(c[1]), "+f"(c[2]), "+f"(c[3])
        : "r"(a[0]), "r"(a[1]), "r"(a[2]), "r"(a[3]), "r"(b[0]), "r"(b[1]));
}
__device__ __forceinline__ void ldm_x4(uint32_t* r, uint32_t addr) {
    asm volatile("ldmatrix.sync.aligned.m8n8.x4.shared.b16 {%0,%1,%2,%3}, [%4];"
        : "=r"(r[0]), "=r"(r[1]), "=r"(r[2]), "=r"(r[3]) : "r"(addr));
}

// ---------------- 1024-pt radix-4 Stockham FFT in shared memory ---------------
__device__ __forceinline__ void fft1024_r4(float2* bA, float2* bB, const float2* TW,
                                           int tid, int inverse)
{
    float2* in = bA;
    float2* out = bB;
    #pragma unroll
    for (int st = 0; st < 5; st++) {
        const int Ns = 1 << (2 * st);
        float2 v0 = in[tid];
        float2 v1 = in[tid + 256];
        float2 v2 = in[tid + 512];
        float2 v3 = in[tid + 768];
        const int t = tid & (Ns - 1);
        if (st > 0) {
            const int ti = t << (8 - 2 * st);
            float2 w1 = TW[ti], w2 = TW[2 * ti], w3 = TW[3 * ti];
            if (inverse) { w1.y = -w1.y; w2.y = -w2.y; w3.y = -w3.y; }
            v1 = cmul(v1, w1); v2 = cmul(v2, w2); v3 = cmul(v3, w3);
        }
        float2 a  = make_float2(v0.x + v2.x, v0.y + v2.y);
        float2 bq = make_float2(v0.x - v2.x, v0.y - v2.y);
        float2 c  = make_float2(v1.x + v3.x, v1.y + v3.y);
        float2 d  = make_float2(v1.x - v3.x, v1.y - v3.y);
        float2 dr = inverse ? make_float2(-d.y, d.x) : make_float2(d.y, -d.x);
        const int idx = ((tid >> (2 * st)) << (2 * st + 2)) + t;
        out[idx]          = make_float2(a.x + c.x,  a.y + c.y);
        out[idx + Ns]     = make_float2(bq.x + dr.x, bq.y + dr.y);
        out[idx + 2 * Ns] = make_float2(a.x - c.x,  a.y - c.y);
        out[idx + 3 * Ns] = make_float2(bq.x - dr.x, bq.y - dr.y);
        __syncthreads();
        float2* tmp = in; in = out; out = tmp;
    }
}

__device__ __forceinline__ void fill_tw768(float2* TW, int tid)
{
    for (int t = tid; t < 768; t += 256) {
        float sv, cv;
        __sincosf(-(2.f * PI_F) * (float)t * (1.f / 1024.f), &sv, &cv);
        TW[t] = make_float2(cv, sv);
    }
}

// ================= weight prep: transpose, FFT, bf16 hi/lo ====================
__global__ void transp_w(const float* __restrict__ W0,
                         const float* __restrict__ W1,
                         const float* __restrict__ W2)
{
    __shared__ float t[32][33];
    const float* W = (blockIdx.z == 0) ? W0 : (blockIdx.z == 1) ? W1 : W2;
    const int tx = threadIdx.x, ty = threadIdx.y;
    const int x0 = blockIdx.x * 32, y0 = blockIdx.y * 32;
    #pragma unroll
    for (int j = 0; j < 4; j++)
        t[ty + j * 8][tx] = W[(size_t)(y0 + ty + j * 8) * Dv + x0 + tx];
    __syncthreads();
    float* Wt = g_Wt + (size_t)blockIdx.z * Dv * Dv;
    #pragma unroll
    for (int j = 0; j < 4; j++)
        Wt[(size_t)(x0 + ty + j * 8) * Dv + y0 + tx] = t[tx][ty + j * 8];
}

// FFT rows of Wt (two packed per block); write What[z][n][d] (float2)
__global__ void fft_w()
{
    __shared__ float2 bA[1024], bB[1024], TW[768];
    const int tid = threadIdx.x;
    const int row0 = blockIdx.x * 2;             // over 3072 rows
    const int z = row0 >> 10, d0 = row0 & 1023;
    const float* w0 = g_Wt + (size_t)row0 * Dv;
    const float* w1 = w0 + Dv;

    fill_tw768(TW, tid);
    for (int d = tid; d < 1024; d += 256)
        bA[d] = make_float2(w0[d], w1[d]);
    __syncthreads();
    fft1024_r4(bA, bB, TW, tid, 0);

    float2* dst = g_Bc2 + (size_t)z * NBv * Dv;
    for (int n = tid; n < 513; n += 256) {
        float2 z0 = bB[n];
        float2 z1 = bB[(1024 - n) & 1023];
        float2 A = make_float2(0.5f * (z0.x + z1.x), 0.5f * (z0.y - z1.y));
        float2 Bc = make_float2(0.5f * (z0.y + z1.y), 0.5f * (z1.x - z0.x));
        dst[(size_t)n * Dv + d0] = A;
        dst[(size_t)n * Dv + d0 + 1] = Bc;
    }
}

// Build B3 bf16 rows: row r = z*1026 + 2n + (0=re,1=im); cols hi|lo|hi
__global__ void convert_B()
{
    const int r = blockIdx.x;
    const int tid = threadIdx.x;
    __nv_bfloat16* row = g_B3 + (size_t)r * Kx;
    if (r >= 3 * 1026) {
        for (int d = tid; d < 1024; d += 256) {
            row[d] = __float2bfloat16_rn(0.f);
            row[1024 + d] = __float2bfloat16_rn(0.f);
            row[2048 + d] = __float2bfloat16_rn(0.f);
        }
        return;
    }
    const int z = r / 1026, rr = r % 1026;
    const int n = rr >> 1, im = rr & 1;
    const float2* src = g_Bc2 + ((size_t)z * NBv + n) * Dv;
    for (int d = tid; d < 1024; d += 256) {
        float2 c = src[d];
        float v = im ? c.y : c.x;
        __nv_bfloat16 h = __float2bfloat16_rn(v);
        __nv_bfloat16 l = __float2bfloat16_rn(v - __bfloat162float(h));
        row[d] = h;
        row[1024 + d] = l;
        row[2048 + d] = h;
    }
}

// A3[m, 0:1024]=hi(x), [1024:2048]=hi(x), [2048:3072]=lo(x)
__global__ void convert_x(const float* __restrict__ X)
{
    size_t i4 = (size_t)blockIdx.x * blockDim.x + threadIdx.x;
    float4 x = ((const float4*)X)[i4];
    size_t m = i4 >> 8;
    size_t kc = (i4 & 255) * 4;
    __nv_bfloat16 h0 = __float2bfloat16_rn(x.x), h1 = __float2bfloat16_rn(x.y);
    __nv_bfloat16 h2 = __float2bfloat16_rn(x.z), h3 = __float2bfloat16_rn(x.w);
    __nv_bfloat16 l0 = __float2bfloat16_rn(x.x - __bfloat162float(h0));
    __nv_bfloat16 l1 = __float2bfloat16_rn(x.y - __bfloat162float(h1));
    __nv_bfloat16 l2 = __float2bfloat16_rn(x.z - __bfloat162float(h2));
    __nv_bfloat16 l3 = __float2bfloat16_rn(x.w - __bfloat162float(h3));
    __nv_bfloat16* row = g_A3 + m * Kx;
    __nv_bfloat162 ha = __halves2bfloat162(h0, h1), hb = __halves2bfloat162(h2, h3);
    __nv_bfloat162 la = __halves2bfloat162(l0, l1), lb = __halves2bfloat162(l2, l3);
    *(__nv_bfloat162*)(row + kc) = ha;          *(__nv_bfloat162*)(row + kc + 2) = hb;
    *(__nv_bfloat162*)(row + 1024 + kc) = ha;   *(__nv_bfloat162*)(row + 1024 + kc + 2) = hb;
    *(__nv_bfloat162*)(row + 2048 + kc) = la;   *(__nv_bfloat162*)(row + 2048 + kc + 2) = lb;
}

// ================= HMMA bf16 GEMM: g_qkv2 = A3 @ B3^T =========================
#define BM 128
#define BN 128
#define BKC 64
#define NCH (Kx / BKC)        // 48
#define STG (BM * 72 * 2)     // 18432 B per tile stage (row stride 144 B)
#define GEMM_SMEM (4 * STG)   // 73728 B

__global__ __launch_bounds__(256, 2) void gemm_mma()
{
    extern __shared__ char smem[];
    const uint32_t sb = smem_u32(smem);
    const int tid = threadIdx.x;
    const int bm = blockIdx.y * BM;
    const int bn = blockIdx.x * BN;

    const int lane = tid & 31, wid = tid >> 5;
    const int g = lane >> 2, tig = lane & 3;
    const int wm = (wid >> 2) * 64, wn = (wid & 3) * 32;

    const int arow = lane & 15;
    const int ahalf = (lane >> 4) & 1;
    const int brow = (lane & 7) + ((lane >> 4) << 3);
    const int bhalf = (lane >> 3) & 1;

    float acc[4][4][4];
    #pragma unroll
    for (int mt = 0; mt < 4; mt++)
        #pragma unroll
        for (int nt = 0; nt < 4; nt++)
            #pragma unroll
            for (int i = 0; i < 4; i++) acc[mt][nt][i] = 0.f;

    auto issue = [&](int ch, int buf) {
        const uint32_t offA = sb + (2 * buf) * STG;
        const uint32_t offB = sb + (2 * buf + 1) * STG;
        const size_t koff = (size_t)ch * BKC;
        #pragma unroll
        for (int t = 0; t < 4; t++) {
            int idx = tid + t * 256;
            int r = idx >> 3, c = idx & 7;
            cp16(offA + r * 144 + c * 16, g_A3 + (size_t)(bm + r) * Kx + koff + c * 8);
        }
        #pragma unroll
        for (int t = 0; t < 4; t++) {
            int idx = tid + t * 256;
            int r = idx >> 3, c = idx & 7;
            cp16(offB + r * 144 + c * 16, g_B3 + (size_t)(bn + r) * Kx + koff + c * 8);
        }
        CP_COMMIT();
    };

    issue(0, 0);
    for (int ch = 0; ch < NCH; ch++) {
        const int cur = ch & 1;
        if (ch + 1 < NCH) {
            issue(ch + 1, cur ^ 1);
            CP_WAIT(1);
        } else {
            CP_WAIT(0);
        }
        __syncthreads();

        const uint32_t sA32 = sb + (2 * cur) * STG;
        const uint32_t sB32 = sb + (2 * cur + 1) * STG;
        #pragma unroll
        for (int ks = 0; ks < 4; ks++) {
            uint32_t af[4][4], bfr[2][4];
            #pragma unroll
            for (int mt = 0; mt < 4; mt++)
                ldm_x4(af[mt], sA32 + (wm + mt * 16 + arow) * 144 + ks * 32 + ahalf * 16);
            #pragma unroll
            for (int np = 0; np < 2; np++)
                ldm_x4(bfr[np], sB32 + (wn + np * 16 + brow) * 144 + ks * 32 + bhalf * 16);
            #pragma unroll
            for (int mt = 0; mt < 4; mt++)
                #pragma unroll
                for (int nt = 0; nt < 4; nt++)
                    mma16816(acc[mt][nt], af[mt], &bfr[nt >> 1][(nt & 1) * 2]);
        }
        __syncthreads();
    }

    #pragma unroll
    for (int mt = 0; mt < 4; mt++) {
        #pragma unroll
        for (int nt = 0; nt < 4; nt++) {
            int row = bm + wm + mt * 16 + g;
            int col = bn + wn + nt * 8 + 2 * tig;
            *(float2*)(g_qkv2 + (size_t)row * NOUT + col) =
                make_float2(acc[mt][nt][0], acc[mt][nt][1]);
            *(float2*)(g_qkv2 + (size_t)(row + 8) * NOUT + col) =
                make_float2(acc[mt][nt][2], acc[mt][nt][3]);
        }
    }
}

// ---------------- spectral prep: normalize K,Q; K*V transposed; conjQ ---------
__global__ void spectral_prep()
{
    const int row = blockIdx.x;                 // b*2048 + s
    const int tid = threadIdx.x;
    const int b = row >> 11, s = row & 2047;
    const float2* base = (const float2*)(g_qkv2 + (size_t)row * NOUT);
    const float2* qr = base;
    const float2* kr = base + 513;
    const float2* vr = base + 1026;
    float2* kvout = (float2*)g_kv4 + (size_t)b * NBv * Sv + s;
    float2* qnout = g_x + (size_t)row * NBv;

    for (int n = tid; n < 513; n += 256) {
        float2 K = kr[n], V = vr[n], Q = qr[n];
        float ik = 1.f / (sqrtf(K.x * K.x + K.y * K.y) + 1e-8f);
        float iq = 1.f / (sqrtf(Q.x * Q.x + Q.y * Q.y) + 1e-8f);
        float2 Ku = make_float2(K.x * ik, K.y * ik);
        kvout[(size_t)n * Sv] = cmul(Ku, V);
        qnout[n] = make_float2(Q.x * iq, -Q.y * iq);
    }
}

// ---------------- inclusive scan over S per (b, bin) --------------------------
__global__ void scan_kernel()
{
    float4* row4 = g_kv4 + (size_t)blockIdx.x * (Sv / 2);
    const int tid = threadIdx.x;

    float4 v4[4];
    #pragma unroll
    for (int i = 0; i < 4; i++) v4[i] = row4[tid * 4 + i];

    float2 inc[8];
    float2 run = make_float2(0.f, 0.f);
    #pragma unroll
    for (int i = 0; i < 8; i++) {
        float2 c = (i & 1) ? make_float2(v4[i >> 1].z, v4[i >> 1].w)
                           : make_float2(v4[i >> 1].x, v4[i >> 1].y);
        run.x += c.x; run.y += c.y;
        inc[i] = run;
    }

    __shared__ float2 ps[256];
    ps[tid] = run;
    __syncthreads();
    for (int off = 1; off < 256; off <<= 1) {
        float2 t = make_float2(0.f, 0.f);
        if (tid >= off) t = ps[tid - off];
        __syncthreads();
        if (tid >= off) { ps[tid].x += t.x; ps[tid].y += t.y; }
        __syncthreads();
    }
    float2 offs = make_float2(ps[tid].x - run.x, ps[tid].y - run.y);

    #pragma unroll
    for (int i = 0; i < 4; i++) {
        float4 o;
        o.x = inc[2 * i].x + offs.x;     o.y = inc[2 * i].y + offs.y;
        o.z = inc[2 * i + 1].x + offs.x; o.w = inc[2 * i + 1].y + offs.y;
        row4[tid * 4 + i] = o;
    }
}

// ---------------- transpose scanned kv + multiply into g_x (RMW) --------------
__global__ void transp_mult()
{
    __shared__ float2 tile[32][33];
    const int tx = threadIdx.x, ty = threadIdx.y;
    const int b = blockIdx.z;
    const int bin0 = blockIdx.x * 32;
    const int s0 = blockIdx.y * 32;

    const float2* kv = (const float2*)g_kv4 + (size_t)b * NBv * Sv;
    #pragma unroll
    for (int j = 0; j < 4; j++) {
        int bin = bin0 + ty + j * 8;
        if (bin < NBv)
            tile[ty + j * 8][tx] = kv[(size_t)bin * Sv + s0 + tx];
    }
    __syncthreads();

    #pragma unroll
    for (int j = 0; j < 4; j++) {
        int s = s0 + ty + j * 8;
        int bin = bin0 + tx;
        if (bin < NBv) {
            size_t off = ((size_t)b * Sv + s) * NBv + bin;
            g_x[off] = cmul(tile[tx][ty + j * 8], g_x[off]);
        }
    }
}

// ---------------- inverse FFT, two rows packed, write real --------------------
__global__ void out_kernel(float* __restrict__ out)
{
    __shared__ float2 bA[1024], bB[1024], TW[768];
    const int tid = threadIdx.x;
    const int row0 = blockIdx.x * 2;

    fill_tw768(TW, tid);
    const float2* X0 = g_x + (size_t)row0 * NBv;
    const float2* X1 = X0 + NBv;
    for (int d = tid; d < 1024; d += 256) {
        float2 x0, x1;
        if (d <= 512) { x0 = X0[d]; x1 = X1[d]; }
        else {
            float2 a0 = X0[1024 - d], a1 = X1[1024 - d];
            x0 = make_float2(a0.x, -a0.y);
            x1 = make_float2(a1.x, -a1.y);
        }
        bA[d] = make_float2(x0.x - x1.y, x0.y + x1.x);   // Z = X0 + i*X1
    }
    __syncthreads();
    fft1024_r4(bA, bB, TW, tid, 1);

    float* o0 = out + (size_t)row0 * Dv;
    float* o1 = o0 + Dv;
    const float scale = 1.f / 1024.f;
    for (int d = tid; d < 1024; d += 256) {
        o0[d] = bB[d].x * scale;
        o1[d] = bB[d].y * scale;
    }
}

// ---------------- launch ------------------------------------------------------
extern "C" void kernel_launch(void* const* d_in, const int* in_sizes, int n_in,
                              void* d_out, int out_size)
{
    (void)in_sizes; (void)n_in; (void)out_size;
    const float* x  = (const float*)d_in[0];
    const float* Wq = (const float*)d_in[1];
    const float* Wk = (const float*)d_in[2];
    const float* Wv = (const float*)d_in[3];
    float* out = (float*)d_out;

    cudaFuncSetAttribute(gemm_mma, cudaFuncAttributeMaxDynamicSharedMemorySize, GEMM_SMEM);

    transp_w<<<dim3(32, 32, 3), dim3(32, 8)>>>(Wq, Wk, Wv);
    fft_w<<<(3 * Dv) / 2, 256>>>();
    convert_B<<<NOUT, 256>>>();
    convert_x<<<(NROW * Dv / 4) / 256, 256>>>(x);

    dim3 gg(NOUT / BN, NROW / BM);    // (25, 64)
    gemm_mma<<<gg, 256, GEMM_SMEM>>>();

    spectral_prep<<<NROW, 256>>>();
    scan_kernel<<<Bv * NBv, 256>>>();
    transp_mult<<<dim3(17, Sv / 32, Bv), dim3(32, 8)>>>();
    out_kernel<<<NROW / 2, 256>>>(out);
}